// round 1
// baseline (speedup 1.0000x reference)
#include <cuda_runtime.h>

// Problem constants (fixed shapes from reference)
#define BB   16
#define CIN  512
#define COUT 512
#define HIN  32
#define RES  64
#define XUW  66          // upsampled intermediate 66x66
#define KTOT 4608        // CIN*9

typedef unsigned long long ull;

// ---------------- device scratch (allocation-free rule: __device__ globals) ----
__device__ float g_styles[BB * CIN];                     // 32 KB
__device__ float g_dcoef[BB * COUT];                     // 32 KB
__device__ float g_s2[COUT * CIN];                       // 1 MB
__device__ float g_wt[(size_t)KTOT * COUT];              // 9.4 MB  : flipped, transposed weight [k][co]
__device__ float g_xu[(size_t)BB * CIN * XUW * XUW];     // 142.7 MB: upsampled input [b*Cin][66][66]

// ---------------- f32x2 helpers ------------------------------------------------
__device__ __forceinline__ ull pk2(float x, float y) {
    ull r;
    asm("mov.b64 %0, {%1, %2};" : "=l"(r) : "r"(__float_as_uint(x)), "r"(__float_as_uint(y)));
    return r;
}
__device__ __forceinline__ ull ffma2(ull a, ull b, ull c) {
    ull d;
    asm("fma.rn.f32x2 %0, %1, %2, %3;" : "=l"(d) : "l"(a), "l"(b), "l"(c));
    return d;
}
__device__ __forceinline__ float2 upk2(ull v) {
    unsigned lo, hi;
    asm("mov.b64 {%0, %1}, %2;" : "=r"(lo), "=r"(hi) : "l"(v));
    return make_float2(__uint_as_float(lo), __uint_as_float(hi));
}

__device__ __forceinline__ float warp_red(float v) {
    v += __shfl_xor_sync(0xffffffffu, v, 16);
    v += __shfl_xor_sync(0xffffffffu, v, 8);
    v += __shfl_xor_sync(0xffffffffu, v, 4);
    v += __shfl_xor_sync(0xffffffffu, v, 2);
    v += __shfl_xor_sync(0xffffffffu, v, 1);
    return v;
}

// ---------------- K1: styles[b][ci] = (w[b] . aw[ci]) / sqrt(512) + ab[ci] -----
__global__ void styles_kernel(const float* __restrict__ w,
                              const float* __restrict__ aw,
                              const float* __restrict__ ab) {
    int g    = blockIdx.x * 8 + (threadIdx.x >> 5);   // 8192 warp-jobs
    int lane = threadIdx.x & 31;
    int b  = g >> 9;
    int ci = g & 511;
    const float* wr = w + b * 512;
    const float* ar = aw + (size_t)ci * 512;
    float s = 0.f;
#pragma unroll
    for (int d = lane; d < 512; d += 32) s += wr[d] * ar[d];
    s = warp_red(s);
    if (lane == 0) g_styles[g] = s * 0.04419417382415922f + ab[ci];  // 1/sqrt(512)
}

// ---------------- K2: s2[co][ci] = sum_{9} weight^2 ----------------------------
__global__ void s2_kernel(const float* __restrict__ weight) {
    int i = blockIdx.x * 256 + threadIdx.x;           // 262144
    const float* p = weight + (size_t)i * 9;
    float s = 0.f;
#pragma unroll
    for (int r = 0; r < 9; r++) s += p[r] * p[r];
    g_s2[i] = s;
}

// ---------------- K3: flipped+transposed weight wt[ci*9+r][co] -----------------
// r indexes the ALREADY-FLIPPED kernel: wt[ci*9+r][co] = weight[co][ci][8-r]
__global__ void wt_kernel(const float* __restrict__ weight) {
    int co = blockIdx.y * 256 + threadIdx.x;
    int k  = blockIdx.x;                              // 0..4607
    int ci = k / 9;
    int r  = k - ci * 9;
    g_wt[(size_t)k * 512 + co] = weight[((size_t)co * 512 + ci) * 9 + (8 - r)];
}

// ---------------- K4: dcoef[b][co] = rsqrt(sum_ci s2*styles^2 + 1e-8) ----------
__global__ void dcoef_kernel() {
    int g    = blockIdx.x * 8 + (threadIdx.x >> 5);
    int lane = threadIdx.x & 31;
    int b  = g >> 9;
    int co = g & 511;
    float s = 0.f;
    for (int ci = lane; ci < 512; ci += 32) {
        float st = g_styles[b * 512 + ci];
        s += g_s2[co * 512 + ci] * st * st;
    }
    s = warp_red(s);
    if (lane == 0) g_dcoef[g] = rsqrtf(s + 1e-8f);
}

// ---------------- K5: upfirdn2d up=2, f=[1,3,3,1]/8, pad 3 ---------------------
// Separable per-parity 2-tap form:
//   p even: xu row taps x[p/2-1]*0.75 + x[p/2]*0.25
//   p odd : x[(p-3)/2]*0.25 + x[(p-1)/2]*0.75     (zeros outside [0,32))
__global__ void upsample_kernel(const float* __restrict__ x) {
    int idx = blockIdx.x * 256 + threadIdx.x;
    if (idx >= BB * CIN * XUW * XUW) return;
    int q  = idx % XUW;
    int t  = idx / XUW;
    int p  = t % XUW;
    int bc = t / XUW;       // b*Cin+ci

    int r0; float wr0, wr1;
    if (p & 1) { r0 = (p - 3) >> 1; wr0 = 0.25f; wr1 = 0.75f; }
    else       { r0 = (p >> 1) - 1; wr0 = 0.75f; wr1 = 0.25f; }
    int c0; float wc0, wc1;
    if (q & 1) { c0 = (q - 3) >> 1; wc0 = 0.25f; wc1 = 0.75f; }
    else       { c0 = (q >> 1) - 1; wc0 = 0.75f; wc1 = 0.25f; }

    const float* xb = x + (size_t)bc * (HIN * HIN);
    float acc = 0.f;
#pragma unroll
    for (int rr = 0; rr < 2; rr++) {
        int r = r0 + rr;
        if ((unsigned)r >= (unsigned)HIN) continue;
        float wr = rr ? wr1 : wr0;
#pragma unroll
        for (int cc = 0; cc < 2; cc++) {
            int c = c0 + cc;
            if ((unsigned)c >= (unsigned)HIN) continue;
            float wc = cc ? wc1 : wc0;
            acc += wr * wc * xb[r * HIN + c];
        }
    }
    g_xu[idx] = acc;
}

// ---------------- K6: main conv (implicit GEMM, fp32x2) ------------------------
// Block: 128 cout x 128 px (2 output rows x 64 cols) for one b.
// K loop: 64 chunks of (8 ci x 9 taps) = 72.
// Thread (ty,tx): 8 co (pairs via f32x2 lanes) x 8 px.
__global__ __launch_bounds__(256, 2)
void conv_kernel(const float* __restrict__ bias,
                 const float* __restrict__ noise,
                 const float* __restrict__ nstr,
                 float* __restrict__ out) {
    __shared__ float As[72][128];     // modulated weights, k-major
    __shared__ float Xs[8][4][68];    // raw xu tile: 8 ci x 4 rows x 66 (+pad)

    int tid  = threadIdx.x;
    int tx   = tid & 15;
    int ty   = tid >> 4;
    int lane = tid & 31;
    int wrp  = tid >> 5;

    int rp  = blockIdx.x;             // row pair 0..31
    int cot = blockIdx.y;             // cout tile 0..3
    int b   = blockIdx.z;
    int i0  = rp * 2;

    const float* xu_b = g_xu + (size_t)b * CIN * (XUW * XUW);
    const float* wt_b = g_wt + cot * 128;

    // per-lane demod coefs for the 4 couts this lane stores into As
    float4 dcv = *(const float4*)&g_dcoef[b * 512 + cot * 128 + lane * 4];

    ull c[4][8];
#pragma unroll
    for (int i = 0; i < 4; i++)
#pragma unroll
        for (int j = 0; j < 8; j++) c[i][j] = 0ull;

    for (int cc = 0; cc < 64; ++cc) {
        // ---- load A tile: 72 k-rows x 128 co, modulated by styles*dcoef ----
        {
            float st = g_styles[b * 512 + cc * 8 + wrp];   // ci of this warp's 9 rows
            float4 sd = make_float4(dcv.x * st, dcv.y * st, dcv.z * st, dcv.w * st);
#pragma unroll
            for (int s = 0; s < 9; s++) {
                int kr = wrp * 9 + s;
                float4 v = *(const float4*)(wt_b + (size_t)(cc * 72 + kr) * 512 + lane * 4);
                v.x *= sd.x; v.y *= sd.y; v.z *= sd.z; v.w *= sd.w;
                *(float4*)&As[kr][lane * 4] = v;
            }
        }
        // ---- load X tile: warp w handles ci_local = w, 4 rows x 66 cols ----
        {
            const float* src = xu_b + ((size_t)(cc * 8 + wrp) * XUW + i0) * XUW;
#pragma unroll
            for (int r = 0; r < 4; r++)
                for (int col = lane; col < 66; col += 32)
                    Xs[wrp][r][col] = src[r * XUW + col];
        }
        __syncthreads();

        // ---- compute ----
#pragma unroll 2
        for (int cil = 0; cil < 8; cil++) {
#pragma unroll
            for (int kh = 0; kh < 3; kh++) {
#pragma unroll
                for (int kw = 0; kw < 3; kw++) {
                    int k = cil * 9 + kh * 3 + kw;
                    float4 a0 = *(const float4*)&As[k][ty * 4];
                    float4 a1 = *(const float4*)&As[k][64 + ty * 4];
                    ull A0 = pk2(a0.x, a0.y), A1 = pk2(a0.z, a0.w);
                    ull A2 = pk2(a1.x, a1.y), A3 = pk2(a1.z, a1.w);
                    const float* x0 = &Xs[cil][kh][tx * 4 + kw];
                    const float* x1 = &Xs[cil][kh + 1][tx * 4 + kw];
#pragma unroll
                    for (int j = 0; j < 4; j++) {
                        ull Bv = pk2(x0[j], x0[j]);
                        c[0][j] = ffma2(A0, Bv, c[0][j]);
                        c[1][j] = ffma2(A1, Bv, c[1][j]);
                        c[2][j] = ffma2(A2, Bv, c[2][j]);
                        c[3][j] = ffma2(A3, Bv, c[3][j]);
                    }
#pragma unroll
                    for (int j = 0; j < 4; j++) {
                        ull Bv = pk2(x1[j], x1[j]);
                        c[0][4 + j] = ffma2(A0, Bv, c[0][4 + j]);
                        c[1][4 + j] = ffma2(A1, Bv, c[1][4 + j]);
                        c[2][4 + j] = ffma2(A2, Bv, c[2][4 + j]);
                        c[3][4 + j] = ffma2(A3, Bv, c[3][4 + j]);
                    }
                }
            }
        }
        __syncthreads();
    }

    // ---- epilogue: + noise*strength, + bias, leaky_relu(0.2) * sqrt(2) ----
    float ns  = __ldg(nstr);
    int col0  = tx * 4;
    float nz[2][4];
#pragma unroll
    for (int rr = 0; rr < 2; rr++)
#pragma unroll
        for (int j = 0; j < 4; j++)
            nz[rr][j] = noise[(i0 + rr) * RES + col0 + j] * ns;

#pragma unroll
    for (int i2 = 0; i2 < 4; i2++) {
        int cl = (i2 < 2) ? (ty * 4 + 2 * i2) : (64 + ty * 4 + 2 * (i2 - 2));
        float2 v[8];
#pragma unroll
        for (int j = 0; j < 8; j++) v[j] = upk2(c[i2][j]);
#pragma unroll
        for (int half = 0; half < 2; half++) {
            int co_g = cot * 128 + cl + half;
            float bv = __ldg(&bias[co_g]);
#pragma unroll
            for (int rr = 0; rr < 2; rr++) {
                float t0 = (half ? v[rr * 4 + 0].y : v[rr * 4 + 0].x) + nz[rr][0] + bv;
                float t1 = (half ? v[rr * 4 + 1].y : v[rr * 4 + 1].x) + nz[rr][1] + bv;
                float t2 = (half ? v[rr * 4 + 2].y : v[rr * 4 + 2].x) + nz[rr][2] + bv;
                float t3 = (half ? v[rr * 4 + 3].y : v[rr * 4 + 3].x) + nz[rr][3] + bv;
                float4 o;
                o.x = fmaxf(t0, 0.2f * t0) * 1.4142135623730951f;
                o.y = fmaxf(t1, 0.2f * t1) * 1.4142135623730951f;
                o.z = fmaxf(t2, 0.2f * t2) * 1.4142135623730951f;
                o.w = fmaxf(t3, 0.2f * t3) * 1.4142135623730951f;
                *(float4*)(out + (((size_t)b * COUT + co_g) * RES + (i0 + rr)) * RES + col0) = o;
            }
        }
    }
}

// ---------------- launch -------------------------------------------------------
extern "C" void kernel_launch(void* const* d_in, const int* in_sizes, int n_in,
                              void* d_out, int out_size) {
    const float* x      = (const float*)d_in[0];  // (16,512,32,32)
    const float* w      = (const float*)d_in[1];  // (16,512)
    const float* aw     = (const float*)d_in[2];  // (512,512)
    const float* ab     = (const float*)d_in[3];  // (512,)
    const float* weight = (const float*)d_in[4];  // (512,512,3,3)
    const float* bias   = (const float*)d_in[5];  // (512,)
    const float* noise  = (const float*)d_in[6];  // (64,64)
    const float* nstr   = (const float*)d_in[7];  // ()
    float* out = (float*)d_out;                   // (16,512,64,64)

    styles_kernel<<<1024, 256>>>(w, aw, ab);
    s2_kernel<<<1024, 256>>>(weight);
    wt_kernel<<<dim3(4608, 2), 256>>>(weight);
    dcoef_kernel<<<1024, 256>>>();                // after styles + s2 (stream-ordered)
    upsample_kernel<<<139392, 256>>>(x);          // 16*512*66*66 / 256
    conv_kernel<<<dim3(32, 4, 16), 256>>>(bias, noise, nstr, out);
}

// round 6
// speedup vs baseline: 2.0522x; 2.0522x over previous
#include <cuda_runtime.h>
#include <cstdint>

#define BB   16
#define CIN  512
#define COUT 512
#define HIN  32
#define RES  64
#define XUW  66
#define PQ   (XUW * XUW)           // 4356

// ---------------- device scratch ----------------------------------------------
__device__ __align__(16) float g_styles[BB * CIN];
__device__ float g_dcoef[BB * COUT];
__device__ float g_s2[COUT * CIN];
__device__ __align__(16) float g_wm[(size_t)BB * 9 * COUT * CIN];   // 151 MB premodulated tf32 weights [b][tap][co][ci]
__device__ float g_xu[(size_t)BB * CIN * PQ];                       // 142.7 MB [b][ci][p][q]
__device__ __align__(16) float g_xut[(size_t)BB * PQ * CIN];        // 142.7 MB [b][pq][ci] tf32-rounded

// ---------------- helpers ------------------------------------------------------
__device__ __forceinline__ uint32_t s2u(const void* p) {
    uint32_t a;
    asm("{ .reg .u64 t; cvta.to.shared.u64 t, %1; cvt.u32.u64 %0, t; }" : "=r"(a) : "l"(p));
    return a;
}
__device__ __forceinline__ uint32_t to_tf32(float x) {
    uint32_t r; asm("cvt.rna.tf32.f32 %0, %1;" : "=r"(r) : "f"(x)); return r;
}
__device__ __forceinline__ void cpasync16(uint32_t dst, const float* src) {
    asm volatile("cp.async.cg.shared.global [%0], [%1], 16;"
                 :: "r"(dst), "l"(__cvta_generic_to_global(src)) : "memory");
}
#define CP_COMMIT() asm volatile("cp.async.commit_group;" ::: "memory")
#define CP_WAIT2()  asm volatile("cp.async.wait_group 2;" ::: "memory")

#define MMA_TF32(c0, c1, c2, c3, a0, a1, a2, a3, b0, b1) \
    asm volatile("mma.sync.aligned.m16n8k8.row.col.f32.tf32.tf32.f32 " \
        "{%0,%1,%2,%3}, {%4,%5,%6,%7}, {%8,%9}, {%0,%1,%2,%3};" \
        : "+f"(c0), "+f"(c1), "+f"(c2), "+f"(c3) \
        : "r"(a0), "r"(a1), "r"(a2), "r"(a3), "r"(b0), "r"(b1))

__device__ __forceinline__ float warp_red(float v) {
    v += __shfl_xor_sync(0xffffffffu, v, 16);
    v += __shfl_xor_sync(0xffffffffu, v, 8);
    v += __shfl_xor_sync(0xffffffffu, v, 4);
    v += __shfl_xor_sync(0xffffffffu, v, 2);
    v += __shfl_xor_sync(0xffffffffu, v, 1);
    return v;
}

// ---------------- K1: styles ---------------------------------------------------
__global__ void styles_kernel(const float* __restrict__ w,
                              const float* __restrict__ aw,
                              const float* __restrict__ ab) {
    int g = blockIdx.x * 8 + (threadIdx.x >> 5);
    int lane = threadIdx.x & 31;
    int b = g >> 9, ci = g & 511;
    const float* wr = w + b * 512;
    const float* ar = aw + (size_t)ci * 512;
    float s = 0.f;
#pragma unroll
    for (int d = lane; d < 512; d += 32) s += wr[d] * ar[d];
    s = warp_red(s);
    if (lane == 0) g_styles[g] = s * 0.04419417382415922f + ab[ci];
}

// ---------------- K2: weight sum-squares ---------------------------------------
__global__ void s2_kernel(const float* __restrict__ weight) {
    int i = blockIdx.x * 256 + threadIdx.x;
    const float* p = weight + (size_t)i * 9;
    float s = 0.f;
#pragma unroll
    for (int r = 0; r < 9; r++) s += p[r] * p[r];
    g_s2[i] = s;
}

// ---------------- K3: dcoef ----------------------------------------------------
__global__ void dcoef_kernel() {
    int g = blockIdx.x * 8 + (threadIdx.x >> 5);
    int lane = threadIdx.x & 31;
    int b = g >> 9, co = g & 511;
    float s = 0.f;
    for (int ci = lane; ci < 512; ci += 32) {
        float st = g_styles[b * 512 + ci];
        s += g_s2[co * 512 + ci] * st * st;
    }
    s = warp_red(s);
    if (lane == 0) g_dcoef[g] = rsqrtf(s + 1e-8f);
}

// ---------------- K4: premodulated weights g_wm[b][tap][co][ci] ----------------
// value = weight[co][ci][8-tap] * styles[b][ci] * dcoef[b][co], tf32-rounded
__global__ void wm_kernel(const float* __restrict__ weight) {
    __shared__ float sw[4608];
    int co = blockIdx.x, b = blockIdx.y, tid = threadIdx.x;
    const float* wp = weight + (size_t)co * 4608;
    for (int i = tid; i < 4608; i += 256) sw[i] = wp[i];
    __syncthreads();
    float dc = g_dcoef[b * 512 + co];
    float* dst = g_wm + ((size_t)(b * 9) * 512 + co) * 512;
#pragma unroll
    for (int t = 0; t < 9; t++) {
        for (int ci = tid; ci < 512; ci += 256) {
            float v = sw[ci * 9 + (8 - t)] * g_styles[b * 512 + ci] * dc;
            dst[(size_t)t * (512 * 512) + ci] = __uint_as_float(to_tf32(v));
        }
    }
}

// ---------------- K5a: upfirdn2d up=2, f=[1,3,3,1]/8, pad 3 --------------------
__global__ void upsample_kernel(const float* __restrict__ x) {
    int idx = blockIdx.x * 256 + threadIdx.x;
    int q = idx % XUW;
    int t = idx / XUW;
    int p = t % XUW;
    int bc = t / XUW;

    int r0; float wr0, wr1;
    if (p & 1) { r0 = (p - 3) >> 1; wr0 = 0.25f; wr1 = 0.75f; }
    else       { r0 = (p >> 1) - 1; wr0 = 0.75f; wr1 = 0.25f; }
    int c0; float wc0, wc1;
    if (q & 1) { c0 = (q - 3) >> 1; wc0 = 0.25f; wc1 = 0.75f; }
    else       { c0 = (q >> 1) - 1; wc0 = 0.75f; wc1 = 0.25f; }

    const float* xb = x + (size_t)bc * (HIN * HIN);
    float acc = 0.f;
#pragma unroll
    for (int rr = 0; rr < 2; rr++) {
        int r = r0 + rr;
        if ((unsigned)r >= (unsigned)HIN) continue;
        float wr = rr ? wr1 : wr0;
#pragma unroll
        for (int cc = 0; cc < 2; cc++) {
            int c = c0 + cc;
            if ((unsigned)c >= (unsigned)HIN) continue;
            acc += wr * (cc ? wc1 : wc0) * xb[r * HIN + c];
        }
    }
    g_xu[idx] = acc;
}

// ---------------- K5b: transpose [ci][pq] -> [pq][ci], tf32-rounded ------------
__global__ void transpose_kernel() {
    __shared__ float s[32][33];
    int tid = threadIdx.x;
    int tx = tid & 31, ty = tid >> 5;
    int pq0 = blockIdx.x * 32, ci0 = blockIdx.y * 32, b = blockIdx.z;

    const float* src = g_xu + ((size_t)b * CIN + ci0) * PQ + pq0;
#pragma unroll
    for (int r = 0; r < 4; r++) {
        int ciL = ty + r * 8;
        s[ciL][tx] = (pq0 + tx < PQ) ? src[(size_t)ciL * PQ + tx] : 0.f;
    }
    __syncthreads();
    float* dst = g_xut + ((size_t)b * PQ + pq0) * CIN + ci0;
#pragma unroll
    for (int r = 0; r < 4; r++) {
        int pqL = ty + r * 8;
        if (pq0 + pqL < PQ)
            dst[(size_t)pqL * CIN + tx] = __uint_as_float(to_tf32(s[tx][pqL]));
    }
}

// ---------------- K6: mma.sync TF32 conv ---------------------------------------
// CTA: 128 co x 128 px (2 output rows x 64 cols). 8 warps 2x4 -> 64co x 32px each.
// K: 288 chunks of 16 (9 taps x 32 ci-chunks). 4-stage cp.async pipeline.
// Smem row stride = 20 floats (80 B): conflict-free for fragment loads.
#define STG_BYTES 20480                 // A 128*80 + B 128*80
#define SMEM_SZ   (4 * STG_BYTES)       // 81920
#define NITER     288

__device__ __forceinline__ void prefetch_tiles(int it, uint32_t sb, int tid,
                                               const float* wm_a, const float* xut_b, int i0) {
    if (it < NITER) {
        uint32_t stg = (uint32_t)(it & 3) * STG_BYTES;
        int tap = it >> 5, chunk = it & 31, ci0 = chunk * 16;
        int kh = tap / 3, kw = tap - kh * 3;
        int row = tid >> 1;                 // 0..127
        int sub = (tid & 1) * 2;            // 0 or 2 (16B units)
        // A: g_wm row (co = cot*128+row), 32 bytes
        const float* asrc = wm_a + (size_t)tap * (512 * 512) + (size_t)row * 512 + ci0 + sub * 4;
        uint32_t adst = sb + stg + row * 80 + sub * 16;
        cpasync16(adst, asrc);
        cpasync16(adst + 16, asrc + 4);
        // B: xut pixel (i0 + py + kh, j + kw), 32 bytes
        int py = row >> 6, j = row & 63;
        const float* bsrc = xut_b + ((size_t)((i0 + py + kh) * XUW + j + kw)) * 512 + ci0 + sub * 4;
        uint32_t bdst = sb + stg + 10240 + row * 80 + sub * 16;
        cpasync16(bdst, bsrc);
        cpasync16(bdst + 16, bsrc + 4);
    }
    CP_COMMIT();
}

__global__ __launch_bounds__(256, 2)
void conv_kernel(const float* __restrict__ bias,
                 const float* __restrict__ noise,
                 const float* __restrict__ nstr,
                 float* __restrict__ out) {
    extern __shared__ char smem[];
    uint32_t sb = s2u(smem);
    int tid = threadIdx.x;
    int wid = tid >> 5, lane = tid & 31;
    int grp = lane >> 2, tig = lane & 3;
    int wco = (wid >> 2) * 64;          // warp co base within 128
    int wpx = (wid & 3) * 32;           // warp px base within 128

    int pt = blockIdx.x;                // 0..31 : output row pair
    int cot = blockIdx.y;               // 0..3
    int b = blockIdx.z;
    int i0 = pt * 2;

    const float* wm_a  = g_wm + (size_t)b * 9 * (512 * 512) + (size_t)(cot * 128) * 512;
    const float* xut_b = g_xut + (size_t)b * PQ * 512;

    float c[4][4][4];
#pragma unroll
    for (int i = 0; i < 4; i++)
#pragma unroll
        for (int j = 0; j < 4; j++)
#pragma unroll
            for (int k = 0; k < 4; k++) c[i][j][k] = 0.f;

    // prologue: stages 0..2
    prefetch_tiles(0, sb, tid, wm_a, xut_b, i0);
    prefetch_tiles(1, sb, tid, wm_a, xut_b, i0);
    prefetch_tiles(2, sb, tid, wm_a, xut_b, i0);

    for (int it = 0; it < NITER; ++it) {
        CP_WAIT2();
        __syncthreads();
        prefetch_tiles(it + 3, sb, tid, wm_a, xut_b, i0);

        const uint32_t* As = (const uint32_t*)(smem + (it & 3) * STG_BYTES);
        const uint32_t* Bs = (const uint32_t*)(smem + (it & 3) * STG_BYTES + 10240);

#pragma unroll
        for (int k8 = 0; k8 < 2; k8++) {
            uint32_t bf0[4], bf1[4];
#pragma unroll
            for (int nt = 0; nt < 4; nt++) {
                const uint32_t* bp = Bs + (wpx + nt * 8 + grp) * 20 + k8 * 8 + tig;
                bf0[nt] = bp[0];
                bf1[nt] = bp[4];
            }
#pragma unroll
            for (int mt = 0; mt < 4; mt++) {
                const uint32_t* ap = As + (wco + mt * 16 + grp) * 20 + k8 * 8 + tig;
                uint32_t a0 = ap[0];
                uint32_t a2 = ap[4];
                uint32_t a1 = ap[8 * 20];
                uint32_t a3 = ap[8 * 20 + 4];
#pragma unroll
                for (int nt = 0; nt < 4; nt++)
                    MMA_TF32(c[mt][nt][0], c[mt][nt][1], c[mt][nt][2], c[mt][nt][3],
                             a0, a1, a2, a3, bf0[nt], bf1[nt]);
            }
        }
    }

    // ---- epilogue ----
    float ns = __ldg(nstr);
#pragma unroll
    for (int mt = 0; mt < 4; mt++) {
#pragma unroll
        for (int h = 0; h < 2; h++) {
            int co_l = wco + mt * 16 + grp + h * 8;
            int co_g = cot * 128 + co_l;
            float bv = __ldg(&bias[co_g]);
            float* outp = out + ((size_t)b * COUT + co_g) * (RES * RES);
#pragma unroll
            for (int nt = 0; nt < 4; nt++) {
                int p0 = wpx + nt * 8 + 2 * tig;
#pragma unroll
                for (int e = 0; e < 2; e++) {
                    int p = p0 + e;
                    int py = p >> 6, j = p & 63;
                    int orow = i0 + py;
                    float v = c[mt][nt][h * 2 + e] + noise[orow * RES + j] * ns + bv;
                    outp[orow * RES + j] = fmaxf(v, 0.2f * v) * 1.4142135623730951f;
                }
            }
        }
    }
}

// ---------------- launch -------------------------------------------------------
extern "C" void kernel_launch(void* const* d_in, const int* in_sizes, int n_in,
                              void* d_out, int out_size) {
    const float* x      = (const float*)d_in[0];
    const float* w      = (const float*)d_in[1];
    const float* aw     = (const float*)d_in[2];
    const float* ab     = (const float*)d_in[3];
    const float* weight = (const float*)d_in[4];
    const float* bias   = (const float*)d_in[5];
    const float* noise  = (const float*)d_in[6];
    const float* nstr   = (const float*)d_in[7];
    float* out = (float*)d_out;

    cudaFuncSetAttribute(conv_kernel, cudaFuncAttributeMaxDynamicSharedMemorySize, SMEM_SZ);

    styles_kernel<<<1024, 256>>>(w, aw, ab);
    s2_kernel<<<1024, 256>>>(weight);
    dcoef_kernel<<<1024, 256>>>();
    wm_kernel<<<dim3(512, 16), 256>>>(weight);
    upsample_kernel<<<139392, 256>>>(x);
    transpose_kernel<<<dim3(137, 16, 16), 256>>>();
    conv_kernel<<<dim3(32, 4, 16), 256, SMEM_SZ>>>(bias, noise, nstr, out);
}

// round 12
// speedup vs baseline: 3.7616x; 1.8329x over previous
#include <cuda_runtime.h>
#include <cuda_fp16.h>
#include <cstdint>

#define BB   16
#define CIN  512
#define COUT 512
#define HIN  32
#define RES  64
#define XUW  66
#define PQ   (XUW * XUW)           // 4356

// ---------------- device scratch ----------------------------------------------
__device__ __align__(16) float g_styles[BB * CIN];
__device__ float g_dcoef[BB * COUT];
__device__ float g_s2[COUT * CIN];
__device__ __align__(16) __half g_wm[(size_t)BB * 9 * COUT * CIN];  // 75.5 MB premodulated fp16 weights [b][tap][co][ci]
__device__ float g_xu[(size_t)BB * CIN * PQ];                       // 142.7 MB [b][ci][p][q]
__device__ __align__(16) __half g_xut[(size_t)BB * PQ * CIN];       // 71.4 MB [b][pq][ci] fp16

// ---------------- helpers ------------------------------------------------------
__device__ __forceinline__ uint32_t s2u(const void* p) {
    uint32_t a;
    asm("{ .reg .u64 t; cvta.to.shared.u64 t, %1; cvt.u32.u64 %0, t; }" : "=r"(a) : "l"(p));
    return a;
}
__device__ __forceinline__ void cpasync16(uint32_t dst, const void* src) {
    asm volatile("cp.async.cg.shared.global [%0], [%1], 16;"
                 :: "r"(dst), "l"(__cvta_generic_to_global(src)) : "memory");
}
#define CP_COMMIT() asm volatile("cp.async.commit_group;" ::: "memory")
#define CP_WAIT2()  asm volatile("cp.async.wait_group 2;" ::: "memory")

// m16n8k16 fp16, fp32 accumulate
#define MMA_F16(c0, c1, c2, c3, a0, a1, a2, a3, b0, b1) \
    asm volatile("mma.sync.aligned.m16n8k16.row.col.f32.f16.f16.f32 " \
        "{%0,%1,%2,%3}, {%4,%5,%6,%7}, {%8,%9}, {%0,%1,%2,%3};" \
        : "+f"(c0), "+f"(c1), "+f"(c2), "+f"(c3) \
        : "r"(a0), "r"(a1), "r"(a2), "r"(a3), "r"(b0), "r"(b1))

__device__ __forceinline__ float warp_red(float v) {
    v += __shfl_xor_sync(0xffffffffu, v, 16);
    v += __shfl_xor_sync(0xffffffffu, v, 8);
    v += __shfl_xor_sync(0xffffffffu, v, 4);
    v += __shfl_xor_sync(0xffffffffu, v, 2);
    v += __shfl_xor_sync(0xffffffffu, v, 1);
    return v;
}

// ---------------- K1: styles ---------------------------------------------------
__global__ void styles_kernel(const float* __restrict__ w,
                              const float* __restrict__ aw,
                              const float* __restrict__ ab) {
    int g = blockIdx.x * 8 + (threadIdx.x >> 5);
    int lane = threadIdx.x & 31;
    int b = g >> 9, ci = g & 511;
    const float* wr = w + b * 512;
    const float* ar = aw + (size_t)ci * 512;
    float s = 0.f;
#pragma unroll
    for (int d = lane; d < 512; d += 32) s += wr[d] * ar[d];
    s = warp_red(s);
    if (lane == 0) g_styles[g] = s * 0.04419417382415922f + ab[ci];
}

// ---------------- K2: weight sum-squares ---------------------------------------
__global__ void s2_kernel(const float* __restrict__ weight) {
    int i = blockIdx.x * 256 + threadIdx.x;
    const float* p = weight + (size_t)i * 9;
    float s = 0.f;
#pragma unroll
    for (int r = 0; r < 9; r++) s += p[r] * p[r];
    g_s2[i] = s;
}

// ---------------- K3: dcoef ----------------------------------------------------
__global__ void dcoef_kernel() {
    int g = blockIdx.x * 8 + (threadIdx.x >> 5);
    int lane = threadIdx.x & 31;
    int b = g >> 9, co = g & 511;
    float s = 0.f;
    for (int ci = lane; ci < 512; ci += 32) {
        float st = g_styles[b * 512 + ci];
        s += g_s2[co * 512 + ci] * st * st;
    }
    s = warp_red(s);
    if (lane == 0) g_dcoef[g] = rsqrtf(s + 1e-8f);
}

// ---------------- K4: premodulated fp16 weights g_wm[b][tap][co][ci] ----------
__global__ void wm_kernel(const float* __restrict__ weight) {
    __shared__ float sw[4608];
    int co = blockIdx.x, b = blockIdx.y, tid = threadIdx.x;
    const float* wp = weight + (size_t)co * 4608;
    for (int i = tid; i < 4608; i += 256) sw[i] = wp[i];
    __syncthreads();
    float dc = g_dcoef[b * 512 + co];
    __half* dst = g_wm + ((size_t)(b * 9) * 512 + co) * 512;
#pragma unroll
    for (int t = 0; t < 9; t++) {
        for (int ci = tid; ci < 512; ci += 256) {
            float v = sw[ci * 9 + (8 - t)] * g_styles[b * 512 + ci] * dc;
            dst[(size_t)t * (512 * 512) + ci] = __float2half_rn(v);
        }
    }
}

// ---------------- K5a: upfirdn2d up=2, f=[1,3,3,1]/8, pad 3 --------------------
__global__ void upsample_kernel(const float* __restrict__ x) {
    int idx = blockIdx.x * 256 + threadIdx.x;
    int q = idx % XUW;
    int t = idx / XUW;
    int p = t % XUW;
    int bc = t / XUW;

    int r0; float wr0, wr1;
    if (p & 1) { r0 = (p - 3) >> 1; wr0 = 0.25f; wr1 = 0.75f; }
    else       { r0 = (p >> 1) - 1; wr0 = 0.75f; wr1 = 0.25f; }
    int c0; float wc0, wc1;
    if (q & 1) { c0 = (q - 3) >> 1; wc0 = 0.25f; wc1 = 0.75f; }
    else       { c0 = (q >> 1) - 1; wc0 = 0.75f; wc1 = 0.25f; }

    const float* xb = x + (size_t)bc * (HIN * HIN);
    float acc = 0.f;
#pragma unroll
    for (int rr = 0; rr < 2; rr++) {
        int r = r0 + rr;
        if ((unsigned)r >= (unsigned)HIN) continue;
        float wr = rr ? wr1 : wr0;
#pragma unroll
        for (int cc = 0; cc < 2; cc++) {
            int c = c0 + cc;
            if ((unsigned)c >= (unsigned)HIN) continue;
            acc += wr * (cc ? wc1 : wc0) * xb[r * HIN + c];
        }
    }
    g_xu[idx] = acc;
}

// ---------------- K5b: transpose [ci][pq] -> [pq][ci], fp16 --------------------
__global__ void transpose_kernel() {
    __shared__ float s[32][33];
    int tid = threadIdx.x;
    int tx = tid & 31, ty = tid >> 5;
    int pq0 = blockIdx.x * 32, ci0 = blockIdx.y * 32, b = blockIdx.z;

    const float* src = g_xu + ((size_t)b * CIN + ci0) * PQ + pq0;
#pragma unroll
    for (int r = 0; r < 4; r++) {
        int ciL = ty + r * 8;
        s[ciL][tx] = (pq0 + tx < PQ) ? src[(size_t)ciL * PQ + tx] : 0.f;
    }
    __syncthreads();
    __half* dst = g_xut + ((size_t)b * PQ + pq0) * CIN + ci0;
#pragma unroll
    for (int r = 0; r < 4; r++) {
        int pqL = ty + r * 8;
        if (pq0 + pqL < PQ)
            dst[(size_t)pqL * CIN + tx] = __float2half_rn(s[tx][pqL]);
    }
}

// ---------------- K6: mma.sync FP16 conv ---------------------------------------
// CTA: 128 co x 128 px. 8 warps 2x4 -> 64co x 32px each.
// K chunk = 32 halves/iter (2 x m16n8k16 k-steps). NITER = 9 taps x 16 = 144.
// Smem row: 64B data, stride 80B (20 words) conflict-free. 4-stage cp.async.
#define STG_BYTES 20480                 // A 128*80 + B 128*80
#define SMEM_SZ   (4 * STG_BYTES)       // 81920
#define NITER     144

__device__ __forceinline__ void prefetch_tiles(int it, uint32_t sb, int tid,
                                               const __half* wm_a, const __half* xut_b, int i0) {
    if (it < NITER) {
        uint32_t stg = (uint32_t)(it & 3) * STG_BYTES;
        int tap = it >> 4, chunk = it & 15, ci0 = chunk * 32;
        int kh = tap / 3, kw = tap - kh * 3;
        int row = tid >> 1;                 // 0..127
        int sub = (tid & 1) * 2;            // 0 or 2 (16B chunks)
        // A: 64B row = 32 halves
        const __half* asrc = wm_a + (size_t)tap * (512 * 512) + (size_t)row * 512 + ci0 + sub * 8;
        uint32_t adst = sb + stg + row * 80 + sub * 16;
        cpasync16(adst, asrc);
        cpasync16(adst + 16, asrc + 8);
        // B
        int py = row >> 6, j = row & 63;
        const __half* bsrc = xut_b + ((size_t)((i0 + py + kh) * XUW + j + kw)) * 512 + ci0 + sub * 8;
        uint32_t bdst = sb + stg + 10240 + row * 80 + sub * 16;
        cpasync16(bdst, bsrc);
        cpasync16(bdst + 16, bsrc + 8);
    }
    CP_COMMIT();
}

__global__ __launch_bounds__(256, 2)
void conv_kernel(const float* __restrict__ bias,
                 const float* __restrict__ noise,
                 const float* __restrict__ nstr,
                 float* __restrict__ out) {
    extern __shared__ char smem[];
    uint32_t sb = s2u(smem);
    int tid = threadIdx.x;
    int wid = tid >> 5, lane = tid & 31;
    int grp = lane >> 2, tig = lane & 3;
    int wco = (wid >> 2) * 64;          // warp co base within 128
    int wpx = (wid & 3) * 32;           // warp px base within 128

    int pt = blockIdx.x;                // 0..31 : output row pair
    int cot = blockIdx.y;               // 0..3
    int b = blockIdx.z;
    int i0 = pt * 2;

    const __half* wm_a  = g_wm + (size_t)b * 9 * (512 * 512) + (size_t)(cot * 128) * 512;
    const __half* xut_b = g_xut + (size_t)b * PQ * 512;

    float c[4][4][4];
#pragma unroll
    for (int i = 0; i < 4; i++)
#pragma unroll
        for (int j = 0; j < 4; j++)
#pragma unroll
            for (int k = 0; k < 4; k++) c[i][j][k] = 0.f;

    prefetch_tiles(0, sb, tid, wm_a, xut_b, i0);
    prefetch_tiles(1, sb, tid, wm_a, xut_b, i0);
    prefetch_tiles(2, sb, tid, wm_a, xut_b, i0);

    for (int it = 0; it < NITER; ++it) {
        CP_WAIT2();
        __syncthreads();
        prefetch_tiles(it + 3, sb, tid, wm_a, xut_b, i0);

        const uint32_t* As = (const uint32_t*)(smem + (it & 3) * STG_BYTES);
        const uint32_t* Bs = (const uint32_t*)(smem + (it & 3) * STG_BYTES + 10240);

#pragma unroll
        for (int s = 0; s < 2; s++) {         // two k16 steps
            uint32_t bf0[4], bf1[4];
#pragma unroll
            for (int nt = 0; nt < 4; nt++) {
                const uint32_t* bp = Bs + (wpx + nt * 8 + grp) * 20 + s * 8 + tig;
                bf0[nt] = bp[0];
                bf1[nt] = bp[4];
            }
#pragma unroll
            for (int mt = 0; mt < 4; mt++) {
                const uint32_t* ap = As + (wco + mt * 16 + grp) * 20 + s * 8 + tig;
                uint32_t a0 = ap[0];            // row grp,   k 2tig..+1
                uint32_t a2 = ap[4];            // row grp,   k 2tig+8..+9
                uint32_t a1 = ap[8 * 20];       // row grp+8, k 2tig..+1
                uint32_t a3 = ap[8 * 20 + 4];   // row grp+8, k 2tig+8..+9
#pragma unroll
                for (int nt = 0; nt < 4; nt++)
                    MMA_F16(c[mt][nt][0], c[mt][nt][1], c[mt][nt][2], c[mt][nt][3],
                            a0, a1, a2, a3, bf0[nt], bf1[nt]);
            }
        }
    }

    // ---- epilogue ----
    float ns = __ldg(nstr);
#pragma unroll
    for (int mt = 0; mt < 4; mt++) {
#pragma unroll
        for (int h = 0; h < 2; h++) {
            int co_l = wco + mt * 16 + grp + h * 8;
            int co_g = cot * 128 + co_l;
            float bv = __ldg(&bias[co_g]);
            float* outp = out + ((size_t)b * COUT + co_g) * (RES * RES);
#pragma unroll
            for (int nt = 0; nt < 4; nt++) {
                int p0 = wpx + nt * 8 + 2 * tig;
#pragma unroll
                for (int e = 0; e < 2; e++) {
                    int p = p0 + e;
                    int py = p >> 6, j = p & 63;
                    int orow = i0 + py;
                    float v = c[mt][nt][h * 2 + e] + noise[orow * RES + j] * ns + bv;
                    outp[orow * RES + j] = fmaxf(v, 0.2f * v) * 1.4142135623730951f;
                }
            }
        }
    }
}

// ---------------- launch -------------------------------------------------------
extern "C" void kernel_launch(void* const* d_in, const int* in_sizes, int n_in,
                              void* d_out, int out_size) {
    const float* x      = (const float*)d_in[0];
    const float* w      = (const float*)d_in[1];
    const float* aw     = (const float*)d_in[2];
    const float* ab     = (const float*)d_in[3];
    const float* weight = (const float*)d_in[4];
    const float* bias   = (const float*)d_in[5];
    const float* noise  = (const float*)d_in[6];
    const float* nstr   = (const float*)d_in[7];
    float* out = (float*)d_out;

    cudaFuncSetAttribute(conv_kernel, cudaFuncAttributeMaxDynamicSharedMemorySize, SMEM_SZ);

    styles_kernel<<<1024, 256>>>(w, aw, ab);
    s2_kernel<<<1024, 256>>>(weight);
    dcoef_kernel<<<1024, 256>>>();
    wm_kernel<<<dim3(512, 16), 256>>>(weight);
    upsample_kernel<<<139392, 256>>>(x);
    transpose_kernel<<<dim3(137, 16, 16), 256>>>();
    conv_kernel<<<dim3(32, 4, 16), 256, SMEM_SZ>>>(bias, noise, nstr, out);
}